// round 7
// baseline (speedup 1.0000x reference)
#include <cuda_runtime.h>

// Mamba-2 SSD forward: b=16, s=1024, h=32, p=64, n=128, block_len=64.
// One CTA per (b,h). 16 chunks processed sequentially with state S[128][64]
// carried in shared memory. All GEMMs TN-form with conflict-free LDS.128.

#define CL    64     // chunk length
#define NDIM  128    // state dim n
#define PDIM  64     // head dim p
#define HNUM  32
#define SEQ   1024
#define NCHUNK 16
#define TPB   256

struct __align__(16) Smem {
    float Ct[NDIM][68];   // C transposed: Ct[n][l]
    float Bt[NDIM][68];   // B transposed: Bt[n][l]
    float S [NDIM][68];   // state: S[n][p]
    float Bd[CL][132];    // B natural, pre-decayed: Bd[l][n] = B[l][n]*dl[l]
    float X [CL][68];     // X natural: X[l][p]
    float Wt[CL][68];     // W transposed: Wt[s][l]
    float acs[CL];
    float e[CL];          // exp(acs[l])
    float einv[CL];       // exp(-acs[l])
    float dl[CL];         // exp(acs[63]-acs[l])
};

__global__ __launch_bounds__(TPB, 1)
void ssd_kernel(const float* __restrict__ gX, const float* __restrict__ gA,
                const float* __restrict__ gB, const float* __restrict__ gC,
                float* __restrict__ gY)
{
    extern __shared__ Smem sm[];
    Smem& s = sm[0];

    const int tid  = threadIdx.x;
    const int lane = tid & 31;
    const int wid  = tid >> 5;
    const int bh   = blockIdx.x;
    const int bb   = bh >> 5;   // / HNUM
    const int hh   = bh & 31;

    // zero state
    for (int i = tid; i < NDIM * 68; i += TPB) (&s.S[0][0])[i] = 0.f;

    const int xbase = bb * SEQ * (HNUM * PDIM) + hh * PDIM;   // + row*2048
    const int bbase = bb * SEQ * (HNUM * NDIM) + hh * NDIM;   // + row*4096
    const int abase = bb * SEQ * HNUM + hh;

    for (int c = 0; c < NCHUNK; ++c) {
        const int srow0 = c * CL;

        // ---------- A cumulative sum + exp factors ----------
        if (tid < CL) {
            float a = gA[abase + (srow0 + tid) * HNUM];
            #pragma unroll
            for (int o = 1; o < 32; o <<= 1) {
                float v = __shfl_up_sync(0xffffffffu, a, o);
                if (lane >= o) a += v;
            }
            s.acs[tid] = a;   // warp-local inclusive scan
        }
        __syncthreads();
        if (tid >= 32 && tid < CL) s.acs[tid] += s.acs[31];
        __syncthreads();
        if (tid < CL) {
            float a    = s.acs[tid];
            float last = s.acs[CL - 1];
            s.e[tid]    = expf(a);
            s.einv[tid] = expf(-a);
            s.dl[tid]   = expf(last - a);
        }
        __syncthreads();

        // ---------- load chunk: X natural; B -> Bt + Bd(decayed); C -> Ct ----------
        #pragma unroll
        for (int k = 0; k < 4; ++k) {           // X: 1024 float4
            int idx = k * TPB + tid;
            int l   = idx >> 4;
            int c4  = (idx & 15) * 4;
            float4 v = *(const float4*)(gX + xbase + (srow0 + l) * 2048 + c4);
            *(float4*)&s.X[l][c4] = v;
        }
        #pragma unroll
        for (int k = 0; k < 8; ++k) {           // B: 2048 float4
            int idx = k * TPB + tid;
            int l   = idx & 63;
            int n0  = (idx >> 6) * 4;
            float4 v = *(const float4*)(gB + bbase + (srow0 + l) * 4096 + n0);
            s.Bt[n0 + 0][l] = v.x; s.Bt[n0 + 1][l] = v.y;
            s.Bt[n0 + 2][l] = v.z; s.Bt[n0 + 3][l] = v.w;
            float d = s.dl[l];
            float4 vd = make_float4(v.x * d, v.y * d, v.z * d, v.w * d);
            *(float4*)&s.Bd[l][n0] = vd;
        }
        #pragma unroll
        for (int k = 0; k < 8; ++k) {           // C: 2048 float4
            int idx = k * TPB + tid;
            int l   = idx & 63;
            int n0  = (idx >> 6) * 4;
            float4 v = *(const float4*)(gC + bbase + (srow0 + l) * 4096 + n0);
            s.Ct[n0 + 0][l] = v.x; s.Ct[n0 + 1][l] = v.y;
            s.Ct[n0 + 2][l] = v.z; s.Ct[n0 + 3][l] = v.w;
        }
        __syncthreads();

        // ---------- GEMM1: G[l][s] = sum_n C[l][n]*B[s][n]; write Wt masked+decayed ----------
        {
            // warp grid 4(l) x 2(s); two warps (wx=1, wy<2) are fully above diag -> skip
            const int wy = wid >> 1, wx = wid & 1;
            const int l0 = wy * 16 + (lane >> 3) * 4;
            const int s0 = wx * 32 + (lane & 7) * 4;
            float acc[4][4] = {};
            if (l0 + 3 >= s0) {
                #pragma unroll 8
                for (int k = 0; k < NDIM; ++k) {
                    float4 av = *(const float4*)&s.Ct[k][l0];
                    float4 bv = *(const float4*)&s.Bt[k][s0];
                    float ar[4] = {av.x, av.y, av.z, av.w};
                    float br[4] = {bv.x, bv.y, bv.z, bv.w};
                    #pragma unroll
                    for (int i = 0; i < 4; ++i)
                        #pragma unroll
                        for (int j = 0; j < 4; ++j)
                            acc[i][j] += ar[i] * br[j];
                }
            }
            #pragma unroll
            for (int i = 0; i < 4; ++i) {
                float el = s.e[l0 + i];
                #pragma unroll
                for (int j = 0; j < 4; ++j) {
                    float w = (l0 + i >= s0 + j) ? acc[i][j] * el * s.einv[s0 + j] : 0.f;
                    s.Wt[s0 + j][l0 + i] = w;
                }
            }
        }
        __syncthreads();

        // ---------- GEMM2+3: Y[l][p] = sum_s Wt[s][l]*X[s][p] + e[l]*sum_n Ct[n][l]*S[n][p] ----------
        {
            const int tx = tid & 15, ty = tid >> 4;
            const int p0 = tx * 4, l0 = ty * 4;
            float acc1[4][4] = {}, acc2[4][4] = {};
            #pragma unroll 8
            for (int k = 0; k < CL; ++k) {
                float4 av = *(const float4*)&s.Wt[k][l0];
                float4 bv = *(const float4*)&s.X[k][p0];
                float ar[4] = {av.x, av.y, av.z, av.w};
                float br[4] = {bv.x, bv.y, bv.z, bv.w};
                #pragma unroll
                for (int i = 0; i < 4; ++i)
                    #pragma unroll
                    for (int j = 0; j < 4; ++j)
                        acc1[i][j] += ar[i] * br[j];
            }
            #pragma unroll 8
            for (int k = 0; k < NDIM; ++k) {
                float4 av = *(const float4*)&s.Ct[k][l0];
                float4 bv = *(const float4*)&s.S[k][p0];
                float ar[4] = {av.x, av.y, av.z, av.w};
                float br[4] = {bv.x, bv.y, bv.z, bv.w};
                #pragma unroll
                for (int i = 0; i < 4; ++i)
                    #pragma unroll
                    for (int j = 0; j < 4; ++j)
                        acc2[i][j] += ar[i] * br[j];
            }
            #pragma unroll
            for (int i = 0; i < 4; ++i) {
                float el = s.e[l0 + i];
                float4 y;
                y.x = acc1[i][0] + el * acc2[i][0];
                y.y = acc1[i][1] + el * acc2[i][1];
                y.z = acc1[i][2] + el * acc2[i][2];
                y.w = acc1[i][3] + el * acc2[i][3];
                *(float4*)(gY + xbase + (srow0 + l0 + i) * 2048 + p0) = y;
            }
        }
        __syncthreads();   // S fully consumed before update

        // ---------- GEMM4: S[n][p] = e[63]*S[n][p] + sum_l Bd[l][n]*X[l][p] ----------
        {
            const int tx = tid & 15, tyn = tid >> 4;
            const int p0 = tx * 4, n0 = tyn * 8;
            const float E = s.e[CL - 1];
            float acc[8][4];
            #pragma unroll
            for (int r = 0; r < 8; ++r) {
                float4 v = *(const float4*)&s.S[n0 + r][p0];
                acc[r][0] = v.x * E; acc[r][1] = v.y * E;
                acc[r][2] = v.z * E; acc[r][3] = v.w * E;
            }
            #pragma unroll 4
            for (int k = 0; k < CL; ++k) {
                float4 bv = *(const float4*)&s.X[k][p0];
                float4 a0 = *(const float4*)&s.Bd[k][n0];
                float4 a1 = *(const float4*)&s.Bd[k][n0 + 4];
                float ar[8] = {a0.x, a0.y, a0.z, a0.w, a1.x, a1.y, a1.z, a1.w};
                float br[4] = {bv.x, bv.y, bv.z, bv.w};
                #pragma unroll
                for (int r = 0; r < 8; ++r)
                    #pragma unroll
                    for (int j = 0; j < 4; ++j)
                        acc[r][j] += ar[r] * br[j];
            }
            #pragma unroll
            for (int r = 0; r < 8; ++r) {
                float4 v = make_float4(acc[r][0], acc[r][1], acc[r][2], acc[r][3]);
                *(float4*)&s.S[n0 + r][p0] = v;
            }
        }
        __syncthreads();   // protect S/Bd/X/Ct before next chunk's loads
    }
}

extern "C" void kernel_launch(void* const* d_in, const int* in_sizes, int n_in,
                              void* d_out, int out_size)
{
    const float* X = (const float*)d_in[0];
    const float* A = (const float*)d_in[1];
    const float* B = (const float*)d_in[2];
    const float* C = (const float*)d_in[3];
    float*       Y = (float*)d_out;

    cudaFuncSetAttribute(ssd_kernel,
                         cudaFuncAttributeMaxDynamicSharedMemorySize,
                         (int)sizeof(Smem));
    ssd_kernel<<<16 * HNUM, TPB, sizeof(Smem)>>>(X, A, B, C, Y);
}

// round 8
// speedup vs baseline: 1.0005x; 1.0005x over previous
#include <cuda_runtime.h>

// Mamba-2 SSD forward: b=16, s=1024, h=32, p=64, n=128, block_len=64.
// One CTA per (b,h). 16 chunks processed sequentially with state S[128][64]
// carried in shared memory. All GEMMs TN-form with conflict-free LDS.128.

#define CL    64     // chunk length
#define NDIM  128    // state dim n
#define PDIM  64     // head dim p
#define HNUM  32
#define SEQ   1024
#define NCHUNK 16
#define TPB   256

struct __align__(16) Smem {
    float Ct[NDIM][68];   // C transposed: Ct[n][l]
    float Bt[NDIM][68];   // B transposed: Bt[n][l]
    float S [NDIM][68];   // state: S[n][p]
    float Bd[CL][132];    // B natural, pre-decayed: Bd[l][n] = B[l][n]*dl[l]
    float X [CL][68];     // X natural: X[l][p]
    float Wt[CL][68];     // W transposed: Wt[s][l]
    float acs[CL];
    float e[CL];          // exp(acs[l])
    float einv[CL];       // exp(-acs[l])
    float dl[CL];         // exp(acs[63]-acs[l])
};

__global__ __launch_bounds__(TPB, 1)
void ssd_kernel(const float* __restrict__ gX, const float* __restrict__ gA,
                const float* __restrict__ gB, const float* __restrict__ gC,
                float* __restrict__ gY)
{
    extern __shared__ Smem sm[];
    Smem& s = sm[0];

    const int tid  = threadIdx.x;
    const int lane = tid & 31;
    const int wid  = tid >> 5;
    const int bh   = blockIdx.x;
    const int bb   = bh >> 5;   // / HNUM
    const int hh   = bh & 31;

    // zero state
    for (int i = tid; i < NDIM * 68; i += TPB) (&s.S[0][0])[i] = 0.f;

    const int xbase = bb * SEQ * (HNUM * PDIM) + hh * PDIM;   // + row*2048
    const int bbase = bb * SEQ * (HNUM * NDIM) + hh * NDIM;   // + row*4096
    const int abase = bb * SEQ * HNUM + hh;

    for (int c = 0; c < NCHUNK; ++c) {
        const int srow0 = c * CL;

        // ---------- A cumulative sum + exp factors ----------
        if (tid < CL) {
            float a = gA[abase + (srow0 + tid) * HNUM];
            #pragma unroll
            for (int o = 1; o < 32; o <<= 1) {
                float v = __shfl_up_sync(0xffffffffu, a, o);
                if (lane >= o) a += v;
            }
            s.acs[tid] = a;   // warp-local inclusive scan
        }
        __syncthreads();
        if (tid >= 32 && tid < CL) s.acs[tid] += s.acs[31];
        __syncthreads();
        if (tid < CL) {
            float a    = s.acs[tid];
            float last = s.acs[CL - 1];
            s.e[tid]    = expf(a);
            s.einv[tid] = expf(-a);
            s.dl[tid]   = expf(last - a);
        }
        __syncthreads();

        // ---------- load chunk: X natural; B -> Bt + Bd(decayed); C -> Ct ----------
        #pragma unroll
        for (int k = 0; k < 4; ++k) {           // X: 1024 float4
            int idx = k * TPB + tid;
            int l   = idx >> 4;
            int c4  = (idx & 15) * 4;
            float4 v = *(const float4*)(gX + xbase + (srow0 + l) * 2048 + c4);
            *(float4*)&s.X[l][c4] = v;
        }
        #pragma unroll
        for (int k = 0; k < 8; ++k) {           // B: 2048 float4
            int idx = k * TPB + tid;
            int l   = idx & 63;
            int n0  = (idx >> 6) * 4;
            float4 v = *(const float4*)(gB + bbase + (srow0 + l) * 4096 + n0);
            s.Bt[n0 + 0][l] = v.x; s.Bt[n0 + 1][l] = v.y;
            s.Bt[n0 + 2][l] = v.z; s.Bt[n0 + 3][l] = v.w;
            float d = s.dl[l];
            float4 vd = make_float4(v.x * d, v.y * d, v.z * d, v.w * d);
            *(float4*)&s.Bd[l][n0] = vd;
        }
        #pragma unroll
        for (int k = 0; k < 8; ++k) {           // C: 2048 float4
            int idx = k * TPB + tid;
            int l   = idx & 63;
            int n0  = (idx >> 6) * 4;
            float4 v = *(const float4*)(gC + bbase + (srow0 + l) * 4096 + n0);
            s.Ct[n0 + 0][l] = v.x; s.Ct[n0 + 1][l] = v.y;
            s.Ct[n0 + 2][l] = v.z; s.Ct[n0 + 3][l] = v.w;
        }
        __syncthreads();

        // ---------- GEMM1: G[l][s] = sum_n C[l][n]*B[s][n]; write Wt masked+decayed ----------
        {
            // warp grid 4(l) x 2(s); two warps (wx=1, wy<2) are fully above diag -> skip
            const int wy = wid >> 1, wx = wid & 1;
            const int l0 = wy * 16 + (lane >> 3) * 4;
            const int s0 = wx * 32 + (lane & 7) * 4;
            float acc[4][4] = {};
            if (l0 + 3 >= s0) {
                #pragma unroll 8
                for (int k = 0; k < NDIM; ++k) {
                    float4 av = *(const float4*)&s.Ct[k][l0];
                    float4 bv = *(const float4*)&s.Bt[k][s0];
                    float ar[4] = {av.x, av.y, av.z, av.w};
                    float br[4] = {bv.x, bv.y, bv.z, bv.w};
                    #pragma unroll
                    for (int i = 0; i < 4; ++i)
                        #pragma unroll
                        for (int j = 0; j < 4; ++j)
                            acc[i][j] += ar[i] * br[j];
                }
            }
            #pragma unroll
            for (int i = 0; i < 4; ++i) {
                float el = s.e[l0 + i];
                #pragma unroll
                for (int j = 0; j < 4; ++j) {
                    float w = (l0 + i >= s0 + j) ? acc[i][j] * el * s.einv[s0 + j] : 0.f;
                    s.Wt[s0 + j][l0 + i] = w;
                }
            }
        }
        __syncthreads();

        // ---------- GEMM2+3: Y[l][p] = sum_s Wt[s][l]*X[s][p] + e[l]*sum_n Ct[n][l]*S[n][p] ----------
        {
            const int tx = tid & 15, ty = tid >> 4;
            const int p0 = tx * 4, l0 = ty * 4;
            float acc1[4][4] = {}, acc2[4][4] = {};
            #pragma unroll 8
            for (int k = 0; k < CL; ++k) {
                float4 av = *(const float4*)&s.Wt[k][l0];
                float4 bv = *(const float4*)&s.X[k][p0];
                float ar[4] = {av.x, av.y, av.z, av.w};
                float br[4] = {bv.x, bv.y, bv.z, bv.w};
                #pragma unroll
                for (int i = 0; i < 4; ++i)
                    #pragma unroll
                    for (int j = 0; j < 4; ++j)
                        acc1[i][j] += ar[i] * br[j];
            }
            #pragma unroll 8
            for (int k = 0; k < NDIM; ++k) {
                float4 av = *(const float4*)&s.Ct[k][l0];
                float4 bv = *(const float4*)&s.S[k][p0];
                float ar[4] = {av.x, av.y, av.z, av.w};
                float br[4] = {bv.x, bv.y, bv.z, bv.w};
                #pragma unroll
                for (int i = 0; i < 4; ++i)
                    #pragma unroll
                    for (int j = 0; j < 4; ++j)
                        acc2[i][j] += ar[i] * br[j];
            }
            #pragma unroll
            for (int i = 0; i < 4; ++i) {
                float el = s.e[l0 + i];
                float4 y;
                y.x = acc1[i][0] + el * acc2[i][0];
                y.y = acc1[i][1] + el * acc2[i][1];
                y.z = acc1[i][2] + el * acc2[i][2];
                y.w = acc1[i][3] + el * acc2[i][3];
                *(float4*)(gY + xbase + (srow0 + l0 + i) * 2048 + p0) = y;
            }
        }
        __syncthreads();   // S fully consumed before update

        // ---------- GEMM4: S[n][p] = e[63]*S[n][p] + sum_l Bd[l][n]*X[l][p] ----------
        {
            const int tx = tid & 15, tyn = tid >> 4;
            const int p0 = tx * 4, n0 = tyn * 8;
            const float E = s.e[CL - 1];
            float acc[8][4];
            #pragma unroll
            for (int r = 0; r < 8; ++r) {
                float4 v = *(const float4*)&s.S[n0 + r][p0];
                acc[r][0] = v.x * E; acc[r][1] = v.y * E;
                acc[r][2] = v.z * E; acc[r][3] = v.w * E;
            }
            #pragma unroll 4
            for (int k = 0; k < CL; ++k) {
                float4 bv = *(const float4*)&s.X[k][p0];
                float4 a0 = *(const float4*)&s.Bd[k][n0];
                float4 a1 = *(const float4*)&s.Bd[k][n0 + 4];
                float ar[8] = {a0.x, a0.y, a0.z, a0.w, a1.x, a1.y, a1.z, a1.w};
                float br[4] = {bv.x, bv.y, bv.z, bv.w};
                #pragma unroll
                for (int r = 0; r < 8; ++r)
                    #pragma unroll
                    for (int j = 0; j < 4; ++j)
                        acc[r][j] += ar[r] * br[j];
            }
            #pragma unroll
            for (int r = 0; r < 8; ++r) {
                float4 v = make_float4(acc[r][0], acc[r][1], acc[r][2], acc[r][3]);
                *(float4*)&s.S[n0 + r][p0] = v;
            }
        }
        __syncthreads();   // protect S/Bd/X/Ct before next chunk's loads
    }
}

extern "C" void kernel_launch(void* const* d_in, const int* in_sizes, int n_in,
                              void* d_out, int out_size)
{
    const float* X = (const float*)d_in[0];
    const float* A = (const float*)d_in[1];
    const float* B = (const float*)d_in[2];
    const float* C = (const float*)d_in[3];
    float*       Y = (float*)d_out;

    cudaFuncSetAttribute(ssd_kernel,
                         cudaFuncAttributeMaxDynamicSharedMemorySize,
                         (int)sizeof(Smem));
    ssd_kernel<<<16 * HNUM, TPB, sizeof(Smem)>>>(X, A, B, C, Y);
}

// round 9
// speedup vs baseline: 1.0005x; 1.0000x over previous
#include <cuda_runtime.h>

// Mamba-2 SSD forward: b=16, s=1024, h=32, p=64, n=128, block_len=64.
// One CTA per (b,h). 16 chunks processed sequentially with state S[128][64]
// carried in shared memory. All GEMMs TN-form with conflict-free LDS.128.

#define CL    64     // chunk length
#define NDIM  128    // state dim n
#define PDIM  64     // head dim p
#define HNUM  32
#define SEQ   1024
#define NCHUNK 16
#define TPB   256

struct __align__(16) Smem {
    float Ct[NDIM][68];   // C transposed: Ct[n][l]
    float Bt[NDIM][68];   // B transposed: Bt[n][l]
    float S [NDIM][68];   // state: S[n][p]
    float Bd[CL][132];    // B natural, pre-decayed: Bd[l][n] = B[l][n]*dl[l]
    float X [CL][68];     // X natural: X[l][p]
    float Wt[CL][68];     // W transposed: Wt[s][l]
    float acs[CL];
    float e[CL];          // exp(acs[l])
    float einv[CL];       // exp(-acs[l])
    float dl[CL];         // exp(acs[63]-acs[l])
};

__global__ __launch_bounds__(TPB, 1)
void ssd_kernel(const float* __restrict__ gX, const float* __restrict__ gA,
                const float* __restrict__ gB, const float* __restrict__ gC,
                float* __restrict__ gY)
{
    extern __shared__ Smem sm[];
    Smem& s = sm[0];

    const int tid  = threadIdx.x;
    const int lane = tid & 31;
    const int wid  = tid >> 5;
    const int bh   = blockIdx.x;
    const int bb   = bh >> 5;   // / HNUM
    const int hh   = bh & 31;

    // zero state
    for (int i = tid; i < NDIM * 68; i += TPB) (&s.S[0][0])[i] = 0.f;

    const int xbase = bb * SEQ * (HNUM * PDIM) + hh * PDIM;   // + row*2048
    const int bbase = bb * SEQ * (HNUM * NDIM) + hh * NDIM;   // + row*4096
    const int abase = bb * SEQ * HNUM + hh;

    for (int c = 0; c < NCHUNK; ++c) {
        const int srow0 = c * CL;

        // ---------- A cumulative sum + exp factors ----------
        if (tid < CL) {
            float a = gA[abase + (srow0 + tid) * HNUM];
            #pragma unroll
            for (int o = 1; o < 32; o <<= 1) {
                float v = __shfl_up_sync(0xffffffffu, a, o);
                if (lane >= o) a += v;
            }
            s.acs[tid] = a;   // warp-local inclusive scan
        }
        __syncthreads();
        if (tid >= 32 && tid < CL) s.acs[tid] += s.acs[31];
        __syncthreads();
        if (tid < CL) {
            float a    = s.acs[tid];
            float last = s.acs[CL - 1];
            s.e[tid]    = expf(a);
            s.einv[tid] = expf(-a);
            s.dl[tid]   = expf(last - a);
        }
        __syncthreads();

        // ---------- load chunk: X natural; B -> Bt + Bd(decayed); C -> Ct ----------
        #pragma unroll
        for (int k = 0; k < 4; ++k) {           // X: 1024 float4
            int idx = k * TPB + tid;
            int l   = idx >> 4;
            int c4  = (idx & 15) * 4;
            float4 v = *(const float4*)(gX + xbase + (srow0 + l) * 2048 + c4);
            *(float4*)&s.X[l][c4] = v;
        }
        #pragma unroll
        for (int k = 0; k < 8; ++k) {           // B: 2048 float4
            int idx = k * TPB + tid;
            int l   = idx & 63;
            int n0  = (idx >> 6) * 4;
            float4 v = *(const float4*)(gB + bbase + (srow0 + l) * 4096 + n0);
            s.Bt[n0 + 0][l] = v.x; s.Bt[n0 + 1][l] = v.y;
            s.Bt[n0 + 2][l] = v.z; s.Bt[n0 + 3][l] = v.w;
            float d = s.dl[l];
            float4 vd = make_float4(v.x * d, v.y * d, v.z * d, v.w * d);
            *(float4*)&s.Bd[l][n0] = vd;
        }
        #pragma unroll
        for (int k = 0; k < 8; ++k) {           // C: 2048 float4
            int idx = k * TPB + tid;
            int l   = idx & 63;
            int n0  = (idx >> 6) * 4;
            float4 v = *(const float4*)(gC + bbase + (srow0 + l) * 4096 + n0);
            s.Ct[n0 + 0][l] = v.x; s.Ct[n0 + 1][l] = v.y;
            s.Ct[n0 + 2][l] = v.z; s.Ct[n0 + 3][l] = v.w;
        }
        __syncthreads();

        // ---------- GEMM1: G[l][s] = sum_n C[l][n]*B[s][n]; write Wt masked+decayed ----------
        {
            // warp grid 4(l) x 2(s); two warps (wx=1, wy<2) are fully above diag -> skip
            const int wy = wid >> 1, wx = wid & 1;
            const int l0 = wy * 16 + (lane >> 3) * 4;
            const int s0 = wx * 32 + (lane & 7) * 4;
            float acc[4][4] = {};
            if (l0 + 3 >= s0) {
                #pragma unroll 8
                for (int k = 0; k < NDIM; ++k) {
                    float4 av = *(const float4*)&s.Ct[k][l0];
                    float4 bv = *(const float4*)&s.Bt[k][s0];
                    float ar[4] = {av.x, av.y, av.z, av.w};
                    float br[4] = {bv.x, bv.y, bv.z, bv.w};
                    #pragma unroll
                    for (int i = 0; i < 4; ++i)
                        #pragma unroll
                        for (int j = 0; j < 4; ++j)
                            acc[i][j] += ar[i] * br[j];
                }
            }
            #pragma unroll
            for (int i = 0; i < 4; ++i) {
                float el = s.e[l0 + i];
                #pragma unroll
                for (int j = 0; j < 4; ++j) {
                    float w = (l0 + i >= s0 + j) ? acc[i][j] * el * s.einv[s0 + j] : 0.f;
                    s.Wt[s0 + j][l0 + i] = w;
                }
            }
        }
        __syncthreads();

        // ---------- GEMM2+3: Y[l][p] = sum_s Wt[s][l]*X[s][p] + e[l]*sum_n Ct[n][l]*S[n][p] ----------
        {
            const int tx = tid & 15, ty = tid >> 4;
            const int p0 = tx * 4, l0 = ty * 4;
            float acc1[4][4] = {}, acc2[4][4] = {};
            #pragma unroll 8
            for (int k = 0; k < CL; ++k) {
                float4 av = *(const float4*)&s.Wt[k][l0];
                float4 bv = *(const float4*)&s.X[k][p0];
                float ar[4] = {av.x, av.y, av.z, av.w};
                float br[4] = {bv.x, bv.y, bv.z, bv.w};
                #pragma unroll
                for (int i = 0; i < 4; ++i)
                    #pragma unroll
                    for (int j = 0; j < 4; ++j)
                        acc1[i][j] += ar[i] * br[j];
            }
            #pragma unroll 8
            for (int k = 0; k < NDIM; ++k) {
                float4 av = *(const float4*)&s.Ct[k][l0];
                float4 bv = *(const float4*)&s.S[k][p0];
                float ar[4] = {av.x, av.y, av.z, av.w};
                float br[4] = {bv.x, bv.y, bv.z, bv.w};
                #pragma unroll
                for (int i = 0; i < 4; ++i)
                    #pragma unroll
                    for (int j = 0; j < 4; ++j)
                        acc2[i][j] += ar[i] * br[j];
            }
            #pragma unroll
            for (int i = 0; i < 4; ++i) {
                float el = s.e[l0 + i];
                float4 y;
                y.x = acc1[i][0] + el * acc2[i][0];
                y.y = acc1[i][1] + el * acc2[i][1];
                y.z = acc1[i][2] + el * acc2[i][2];
                y.w = acc1[i][3] + el * acc2[i][3];
                *(float4*)(gY + xbase + (srow0 + l0 + i) * 2048 + p0) = y;
            }
        }
        __syncthreads();   // S fully consumed before update

        // ---------- GEMM4: S[n][p] = e[63]*S[n][p] + sum_l Bd[l][n]*X[l][p] ----------
        {
            const int tx = tid & 15, tyn = tid >> 4;
            const int p0 = tx * 4, n0 = tyn * 8;
            const float E = s.e[CL - 1];
            float acc[8][4];
            #pragma unroll
            for (int r = 0; r < 8; ++r) {
                float4 v = *(const float4*)&s.S[n0 + r][p0];
                acc[r][0] = v.x * E; acc[r][1] = v.y * E;
                acc[r][2] = v.z * E; acc[r][3] = v.w * E;
            }
            #pragma unroll 4
            for (int k = 0; k < CL; ++k) {
                float4 bv = *(const float4*)&s.X[k][p0];
                float4 a0 = *(const float4*)&s.Bd[k][n0];
                float4 a1 = *(const float4*)&s.Bd[k][n0 + 4];
                float ar[8] = {a0.x, a0.y, a0.z, a0.w, a1.x, a1.y, a1.z, a1.w};
                float br[4] = {bv.x, bv.y, bv.z, bv.w};
                #pragma unroll
                for (int r = 0; r < 8; ++r)
                    #pragma unroll
                    for (int j = 0; j < 4; ++j)
                        acc[r][j] += ar[r] * br[j];
            }
            #pragma unroll
            for (int r = 0; r < 8; ++r) {
                float4 v = make_float4(acc[r][0], acc[r][1], acc[r][2], acc[r][3]);
                *(float4*)&s.S[n0 + r][p0] = v;
            }
        }
        __syncthreads();   // protect S/Bd/X/Ct before next chunk's loads
    }
}

extern "C" void kernel_launch(void* const* d_in, const int* in_sizes, int n_in,
                              void* d_out, int out_size)
{
    const float* X = (const float*)d_in[0];
    const float* A = (const float*)d_in[1];
    const float* B = (const float*)d_in[2];
    const float* C = (const float*)d_in[3];
    float*       Y = (float*)d_out;

    cudaFuncSetAttribute(ssd_kernel,
                         cudaFuncAttributeMaxDynamicSharedMemorySize,
                         (int)sizeof(Smem));
    ssd_kernel<<<16 * HNUM, TPB, sizeof(Smem)>>>(X, A, B, C, Y);
}